// round 15
// baseline (speedup 1.0000x reference)
#include <cuda_runtime.h>
#include <cstdint>

#define Bb 8
#define Tt 2048
#define Cc 1024
#define HS 64
#define CH 4              // key-tiles (128 keys) per split-KV chunk
#define NSLOT 4
#define WPB 40            // sum_{rb=0}^{15} ceil((rb+1)/4)

__device__ __align__(16) float g_Q[Bb*Tt*HS];
__device__ __align__(16) float g_K[Bb*Tt*HS];      // tf32-rounded
__device__ __align__(16) float g_V[Bb*Tt*HS];      // tf32-rounded
__device__ __align__(16) float g_Op[NSLOT*Bb*Tt*HS];
__device__ __align__(16) float g_Lp[NSLOT*Bb*Tt];
__device__ __align__(16) uint32_t g_Bpk[64 * 3072]; // 64 k-chunks x 192 n-rows x 16 words

__device__ __forceinline__ uint32_t tf32r(float f) {
    uint32_t r; asm("cvt.rna.tf32.f32 %0, %1;" : "=r"(r) : "f"(f)); return r;
}
__device__ __forceinline__ float ex2f(float x) {
    float r; asm("ex2.approx.f32 %0, %1;" : "=f"(r) : "f"(x)); return r;
}
__device__ __forceinline__ void mma8(float4& d, uint32_t a0, uint32_t a1, uint32_t a2, uint32_t a3,
                                     uint32_t b0, uint32_t b1) {
    asm("mma.sync.aligned.m16n8k8.row.col.f32.tf32.tf32.f32 "
        "{%0,%1,%2,%3}, {%4,%5,%6,%7}, {%8,%9}, {%0,%1,%2,%3};"
        : "+f"(d.x), "+f"(d.y), "+f"(d.z), "+f"(d.w)
        : "r"(a0), "r"(a1), "r"(a2), "r"(a3), "r"(b0), "r"(b1));
}
__device__ __forceinline__ uint32_t smem_u32(const void* p) {
    uint32_t a;
    asm("{ .reg .u64 t; cvta.to.shared.u64 t, %1; cvt.u32.u64 %0, t; }" : "=r"(a) : "l"(p));
    return a;
}
__device__ __forceinline__ void cpa16(uint32_t dst, const void* src) {
    asm volatile("cp.async.cg.shared.global [%0], [%1], 16;" :: "r"(dst), "l"(src));
}
#define CP_COMMIT() asm volatile("cp.async.commit_group;" ::: "memory")
#define CP_WAIT0()  asm volatile("cp.async.wait_group 0;" ::: "memory")

// ============================================================================
// Prep (unchanged): weights -> permuted + XOR-swizzled tf32 image.
// Word layout of row n (16 words): word[((k&3)^(n&3))*4 + (k>>2)] = W[k][n].
// ============================================================================
__global__ __launch_bounds__(256) void prep_b(
    const float* __restrict__ Wq, const float* __restrict__ Wk, const float* __restrict__ Wv)
{
    const int ch = blockIdx.x;
    #pragma unroll
    for (int i = 0; i < 12; i++) {
        const int idx = threadIdx.x + i * 256;    // 0..3071
        const int n = idx >> 4, wd = idx & 15;
        const int k = ((wd & 3) << 2) | ((wd >> 2) ^ (n & 3));
        const float* W = (n < 64) ? Wq : (n < 128) ? Wk : Wv;
        g_Bpk[ch * 3072 + idx] = tf32r(W[(size_t)(ch * 16 + k) * HS + (n & 63)]);
    }
}

// ============================================================================
// Fused QKV: CTA 64(m) x 96(n), 256 threads, 8 warps (2m x 4n), warp tile
// 32x24 (acc 24 regs) -> 3 CTAs/SM = 24 warps/SM. Grid 512 (256 m x 2 n).
// XOR-swizzled 16-word rows; all fragment loads conflict-free LDS.128.
// 2-stage ping-pong, 1 sync/iter, 20KB smem.
//
// smem words: A stage s at s*1024 (64 rows x 16w); B stage s at 2048+s*1536.
// ============================================================================
#define QKV_SMEM (5120 * 4)   // 20480 bytes
__global__ __launch_bounds__(256, 3) void qkv_mma(const float* __restrict__ x)
{
    extern __shared__ uint32_t sm[];
    const int tid = threadIdx.x;
    const int w = tid >> 5, lane = tid & 31;
    const int g = lane >> 2, t = lane & 3;
    const int wm = w >> 2, wn = w & 3;
    const int m0 = (blockIdx.x >> 1) * 64;
    const int cb0 = (blockIdx.x & 1) * 96;

    float4 acc[2][3];
    #pragma unroll
    for (int i = 0; i < 2; i++)
        #pragma unroll
        for (int j = 0; j < 3; j++) acc[i][j] = make_float4(0.f, 0.f, 0.f, 0.f);

    const int ar = tid >> 2, aq0 = tid & 3;   // A staging: row ar, quarter aq0
    const int asw = ar & 3;
    const bool bldr = (tid < 96);
    const uint32_t sbase = smem_u32(sm);
    const float* xrow = x + (size_t)(m0 + ar) * Cc;
    const uint32_t* bsrc = g_Bpk + (cb0 + tid) * 16;   // valid when bldr

    // prologue: B chunk 0 -> stage 0; A chunk 0 -> regs
    if (bldr) {
        const uint32_t d0 = sbase + (2048u + (uint32_t)tid * 16) * 4;
        #pragma unroll
        for (int j = 0; j < 4; j++) cpa16(d0 + j * 16, bsrc + j * 4);
    }
    CP_COMMIT();
    float4 a_s = *(const float4*)(xrow + aq0 * 4);

    const int fsw = ((t ^ (g & 3)) << 2);
    const int raw = (wm * 32 + g) * 16;              // A warp row base (words)
    const int rbw = (wn * 24 + g) * 16;              // B warp row base (words)

    #pragma unroll 1
    for (int ch = 0; ch < 64; ch++) {
        const int s = ch & 1;
        // stage A(ch): R11 word layout (scalar STS)
        {
            uint32_t* A = sm + s * 1024 + ar * 16 + aq0;
            A[((0 ^ asw) << 2)] = tf32r(a_s.x);
            A[((1 ^ asw) << 2)] = tf32r(a_s.y);
            A[((2 ^ asw) << 2)] = tf32r(a_s.z);
            A[((3 ^ asw) << 2)] = tf32r(a_s.w);
        }
        CP_WAIT0();
        __syncthreads();
        if (ch < 63) {
            if (bldr) {
                const uint32_t* src = bsrc + (size_t)(ch + 1) * 3072;
                const uint32_t dst = sbase + (2048u + (uint32_t)(s ^ 1) * 1536u + (uint32_t)tid * 16) * 4;
                #pragma unroll
                for (int j = 0; j < 4; j++) cpa16(dst + j * 16, src + j * 4);
            }
            CP_COMMIT();
            a_s = *(const float4*)(xrow + (ch + 1) * 16 + aq0 * 4);
        }
        // fragments: uint4 = k in {t, t+4, t+8, t+12}
        const uint32_t* Ap = sm + s * 1024 + raw + fsw;
        const uint4 A0a = *(const uint4*)(Ap);
        const uint4 A8a = *(const uint4*)(Ap + 128);
        const uint4 A0b = *(const uint4*)(Ap + 256);
        const uint4 A8b = *(const uint4*)(Ap + 384);
        const uint32_t* Bp = sm + 2048 + s * 1536 + rbw + fsw;
        #pragma unroll
        for (int ns = 0; ns < 3; ns++) {
            const uint4 Bv = *(const uint4*)(Bp + ns * 128);
            mma8(acc[0][ns], A0a.x, A8a.x, A0a.y, A8a.y, Bv.x, Bv.y);   // kk=0
            mma8(acc[0][ns], A0a.z, A8a.z, A0a.w, A8a.w, Bv.z, Bv.w);   // kk=1
            mma8(acc[1][ns], A0b.x, A8b.x, A0b.y, A8b.y, Bv.x, Bv.y);
            mma8(acc[1][ns], A0b.z, A8b.z, A0b.w, A8b.w, Bv.z, Bv.w);
        }
    }
    // epilogue: Q raw; K,V tf32-rounded plain layout
    #pragma unroll
    for (int sub = 0; sub < 2; sub++) {
        #pragma unroll
        for (int ns = 0; ns < 3; ns++) {
            const int cbg = cb0 + wn * 24 + ns * 8;
            float* base = (cbg < 64) ? g_Q : (cbg < 128) ? g_K : g_V;
            const bool rnd = (cbg >= 64);
            const int c = (cbg & 63) + 2 * t;
            const size_t r = (size_t)(m0 + wm * 32 + sub * 16 + g);
            float4 v = acc[sub][ns];
            if (rnd) {
                v.x = __uint_as_float(tf32r(v.x)); v.y = __uint_as_float(tf32r(v.y));
                v.z = __uint_as_float(tf32r(v.z)); v.w = __uint_as_float(tf32r(v.w));
            }
            *(float2*)(base + r * HS + c)       = make_float2(v.x, v.y);
            *(float2*)(base + (r + 8) * HS + c) = make_float2(v.z, v.w);
        }
    }
}

// ============================================================================
// Split-KV causal attention (exact R8 best): fused per-8-key S->softmax->PV,
// 2 CTAs/SM, K/V staged raw via cp.async, scalar fragment gathers.
// ============================================================================
#define KLDK 68
#define KLDV 72
#define SMEM_ATTN ((128 * KLDK + 128 * KLDV) * 4)

__global__ __launch_bounds__(256, 2) void attn_part(void)
{
    extern __shared__ uint32_t smv[];
    uint32_t* Ks = smv;
    uint32_t* Vs = smv + 128 * KLDK;
    const uint32_t ks_b = smem_u32(Ks), vs_b = smem_u32(Vs);

    const int item = (gridDim.x - 1) - blockIdx.x;
    const int b = item / WPB;
    int r = item % WPB, rb = 0;
    #pragma unroll 1
    while (true) { int n = (rb + CH) >> 2; if (r < n) break; r -= n; rb++; }
    const int chunk = r;
    const int t0 = chunk * CH;
    const int t1 = (t0 + CH < rb + 1) ? (t0 + CH) : (rb + 1);
    const int qbase = rb * 128;

    const int tid = threadIdx.x;
    const int w = tid >> 5, lane = tid & 31;
    const int g = lane >> 2, t = lane & 3;
    const int qrow_lo = qbase + w * 16 + g;
    const int qrow_hi = qrow_lo + 8;

    const float qscale = 1.4426950408889634f / 32.0f;
    uint32_t aq[8][4];
    {
        const float* r0 = g_Q + ((size_t)b * Tt + qrow_lo) * HS;
        const float* r1 = r0 + 8 * HS;
        #pragma unroll
        for (int kk = 0; kk < 8; kk++) {
            aq[kk][0] = tf32r(r0[kk * 8 + t] * qscale);
            aq[kk][1] = tf32r(r1[kk * 8 + t] * qscale);
            aq[kk][2] = tf32r(r0[kk * 8 + t + 4] * qscale);
            aq[kk][3] = tf32r(r1[kk * 8 + t + 4] * qscale);
        }
    }

    float4 acc_o[8];
    #pragma unroll
    for (int i = 0; i < 8; i++) acc_o[i] = make_float4(0.f, 0.f, 0.f, 0.f);
    float lsum_lo = 0.f, lsum_hi = 0.f;

    const float* Kg = g_K + (size_t)b * Tt * HS;
    const float* Vg = g_V + (size_t)b * Tt * HS;
    const int srcq0 = (lane & ~3) | (t >> 1);
    const int srcq1 = srcq0 | 2;
    const bool odd = (t & 1);

    #pragma unroll 1
    for (int tt = t0; tt < t1; tt++) {
        const int j0 = tt * 128;
        __syncthreads();
        #pragma unroll
        for (int i = 0; i < 8; i++) {
            int u = tid + i * 256;
            int rr = u >> 4, c = (u & 15) * 4;
            cpa16(ks_b + (uint32_t)(rr * KLDK + c) * 4, Kg + (size_t)(j0 + rr) * HS + c);
            cpa16(vs_b + (uint32_t)(rr * KLDV + c) * 4, Vg + (size_t)(j0 + rr) * HS + c);
        }
        CP_COMMIT();
        CP_WAIT0();
        __syncthreads();

        const bool last_tile = (tt == rb);
        #pragma unroll 1
        for (int ns = 0; ns < 16; ns++) {
            float4 cs = make_float4(0.f, 0.f, 0.f, 0.f);
            #pragma unroll
            for (int kk = 0; kk < 8; kk++) {
                uint32_t b0 = Ks[(ns * 8 + g) * KLDK + kk * 8 + t];
                uint32_t b1 = Ks[(ns * 8 + g) * KLDK + kk * 8 + t + 4];
                mma8(cs, aq[kk][0], aq[kk][1], aq[kk][2], aq[kk][3], b0, b1);
            }
            float px = ex2f(cs.x), py = ex2f(cs.y), pz = ex2f(cs.z), pw = ex2f(cs.w);
            if (last_tile) {
                const int cx = j0 + ns * 8 + 2 * t, cy = cx + 1;
                if (cx > qrow_lo) px = 0.f;
                if (cy > qrow_lo) py = 0.f;
                if (cx > qrow_hi) pz = 0.f;
                if (cy > qrow_hi) pw = 0.f;
            }
            uint32_t ux = tf32r(px), uy = tf32r(py), uz = tf32r(pz), uw = tf32r(pw);
            lsum_lo += __uint_as_float(ux) + __uint_as_float(uy);
            lsum_hi += __uint_as_float(uz) + __uint_as_float(uw);
            uint32_t xA = __shfl_sync(0xffffffffu, ux, srcq0);
            uint32_t yA = __shfl_sync(0xffffffffu, uy, srcq0);
            uint32_t zA = __shfl_sync(0xffffffffu, uz, srcq0);
            uint32_t wA = __shfl_sync(0xffffffffu, uw, srcq0);
            uint32_t xB = __shfl_sync(0xffffffffu, ux, srcq1);
            uint32_t yB = __shfl_sync(0xffffffffu, uy, srcq1);
            uint32_t zB = __shfl_sync(0xffffffffu, uz, srcq1);
            uint32_t wB = __shfl_sync(0xffffffffu, uw, srcq1);
            uint32_t a0 = odd ? yA : xA;
            uint32_t a1 = odd ? wA : zA;
            uint32_t a2 = odd ? yB : xB;
            uint32_t a3 = odd ? wB : zB;
            #pragma unroll
            for (int ns2 = 0; ns2 < 8; ns2++) {
                uint32_t b0 = Vs[(ns * 8 + t) * KLDV + ns2 * 8 + g];
                uint32_t b1 = Vs[(ns * 8 + t + 4) * KLDV + ns2 * 8 + g];
                mma8(acc_o[ns2], a0, a1, a2, a3, b0, b1);
            }
        }
    }

    float llo = lsum_lo;
    llo += __shfl_xor_sync(0xffffffffu, llo, 1);
    llo += __shfl_xor_sync(0xffffffffu, llo, 2);
    float lhi = lsum_hi;
    lhi += __shfl_xor_sync(0xffffffffu, lhi, 1);
    lhi += __shfl_xor_sync(0xffffffffu, lhi, 2);

    float* baseo = g_Op + (((size_t)chunk * Bb + b) * Tt + qrow_lo) * HS;
    #pragma unroll
    for (int ns2 = 0; ns2 < 8; ns2++) {
        *(float2*)(baseo + ns2 * 8 + 2 * t)          = make_float2(acc_o[ns2].x, acc_o[ns2].y);
        *(float2*)(baseo + 8 * HS + ns2 * 8 + 2 * t) = make_float2(acc_o[ns2].z, acc_o[ns2].w);
    }
    if (t == 0) {
        g_Lp[((size_t)chunk * Bb + b) * Tt + qrow_lo] = llo;
        g_Lp[((size_t)chunk * Bb + b) * Tt + qrow_hi] = lhi;
    }
}

// ============================================================================
// Combine (R8): float4/thread, <=4 slots.
// ============================================================================
__global__ __launch_bounds__(256) void attn_combine(float* __restrict__ out)
{
    const int idx4 = blockIdx.x * 256 + threadIdx.x;
    const int row  = idx4 >> 4;
    const int d4   = (idx4 & 15) * 4;
    const int trow = row & (Tt - 1);
    const int b    = row >> 11;
    const int rb   = trow >> 7;
    const int nch  = (rb + CH) >> 2;

    float4 o = make_float4(0.f, 0.f, 0.f, 0.f);
    float l = 0.f;
    #pragma unroll
    for (int s = 0; s < NSLOT; s++) {
        if (s < nch) {
            float4 v = *(const float4*)(g_Op + (((size_t)s * Bb + b) * Tt + trow) * HS + d4);
            o.x += v.x; o.y += v.y; o.z += v.z; o.w += v.w;
            l += g_Lp[((size_t)s * Bb + b) * Tt + trow];
        }
    }
    const float rl = 1.0f / l;
    *(float4*)(out + (size_t)row * HS + d4) =
        make_float4(o.x * rl, o.y * rl, o.z * rl, o.w * rl);
}

// ============================================================================
extern "C" void kernel_launch(void* const* d_in, const int* in_sizes, int n_in,
                              void* d_out, int out_size)
{
    const float* x  = (const float*)d_in[0];
    const float* Wq = (const float*)d_in[1];
    const float* Wk = (const float*)d_in[2];
    const float* Wv = (const float*)d_in[3];
    float* out = (float*)d_out;

    prep_b<<<64, 256>>>(Wq, Wk, Wv);

    qkv_mma<<<512, 256, QKV_SMEM>>>(x);

    cudaFuncSetAttribute(attn_part, cudaFuncAttributeMaxDynamicSharedMemorySize, SMEM_ATTN);
    attn_part<<<Bb * WPB, 256, SMEM_ATTN>>>();

    attn_combine<<<(Bb * Tt * (HS / 4)) / 256, 256>>>(out);
}

// round 16
// speedup vs baseline: 1.3061x; 1.3061x over previous
#include <cuda_runtime.h>
#include <cstdint>

#define Bb 8
#define Tt 2048
#define Cc 1024
#define HS 64
#define CH 4              // key-tiles (128 keys) per split-KV chunk
#define NSLOT 4
#define WPB 40            // sum_{rb=0}^{15} ceil((rb+1)/4)

__device__ __align__(16) float g_Q[Bb*Tt*HS];
__device__ __align__(16) float g_K[Bb*Tt*HS];      // tf32-rounded
__device__ __align__(16) float g_V[Bb*Tt*HS];      // tf32-rounded
__device__ __align__(16) float g_Op[NSLOT*Bb*Tt*HS];
__device__ __align__(16) float g_Lp[NSLOT*Bb*Tt];
__device__ __align__(16) uint32_t g_Bpk[64 * 3072]; // 64 k-chunks x 192 n-rows x 16 words

__device__ __forceinline__ uint32_t tf32r(float f) {
    uint32_t r; asm("cvt.rna.tf32.f32 %0, %1;" : "=r"(r) : "f"(f)); return r;
}
__device__ __forceinline__ float ex2f(float x) {
    float r; asm("ex2.approx.f32 %0, %1;" : "=f"(r) : "f"(x)); return r;
}
__device__ __forceinline__ void mma8(float4& d, uint32_t a0, uint32_t a1, uint32_t a2, uint32_t a3,
                                     uint32_t b0, uint32_t b1) {
    asm("mma.sync.aligned.m16n8k8.row.col.f32.tf32.tf32.f32 "
        "{%0,%1,%2,%3}, {%4,%5,%6,%7}, {%8,%9}, {%0,%1,%2,%3};"
        : "+f"(d.x), "+f"(d.y), "+f"(d.z), "+f"(d.w)
        : "r"(a0), "r"(a1), "r"(a2), "r"(a3), "r"(b0), "r"(b1));
}
__device__ __forceinline__ uint32_t smem_u32(const void* p) {
    uint32_t a;
    asm("{ .reg .u64 t; cvta.to.shared.u64 t, %1; cvt.u32.u64 %0, t; }" : "=r"(a) : "l"(p));
    return a;
}
__device__ __forceinline__ void cpa16(uint32_t dst, const void* src) {
    asm volatile("cp.async.cg.shared.global [%0], [%1], 16;" :: "r"(dst), "l"(src));
}
#define CP_COMMIT() asm volatile("cp.async.commit_group;" ::: "memory")
#define CP_WAIT0()  asm volatile("cp.async.wait_group 0;" ::: "memory")
#define CP_WAIT2()  asm volatile("cp.async.wait_group 2;" ::: "memory")

// ============================================================================
// Prep (unchanged R11): weights -> permuted + XOR-swizzled tf32 image.
// Word layout of row n (16 words): word[((k&3)^(n&3))*4 + (k>>2)] = W[k][n].
// ============================================================================
__global__ __launch_bounds__(256) void prep_b(
    const float* __restrict__ Wq, const float* __restrict__ Wk, const float* __restrict__ Wv)
{
    const int ch = blockIdx.x;
    #pragma unroll
    for (int i = 0; i < 12; i++) {
        const int idx = threadIdx.x + i * 256;    // 0..3071
        const int n = idx >> 4, wd = idx & 15;
        const int k = ((wd & 3) << 2) | ((wd >> 2) ^ (n & 3));
        const float* W = (n < 64) ? Wq : (n < 128) ? Wk : Wv;
        g_Bpk[ch * 3072 + idx] = tf32r(W[(size_t)(ch * 16 + k) * HS + (n & 63)]);
    }
}

// ============================================================================
// Fused QKV: CTA 64x192, BK=16, 8 warps (2m x 4n), warp tile 32x48, x read
// ONCE. ALL global traffic via cp.async: x raw + B prepped, 4-stage rings,
// wait_group 2 (3 groups in flight => ~3x MLP on the x path, zero regs).
// Per iter: self-issued xraw LDS.128 -> cvt -> swizzled A-frag STS -> sync
// -> compute (R11 conflict-free LDS.128 fragments). 2 CTAs/SM, 72KB smem.
//
// smem words: AF(s2)=s2*1024 (2 stages); XR(s4)=2048+s4*1024 (4 stages);
//             BF(s4)=6144+s4*3072 (4 stages).
// ============================================================================
#define QKV_SMEM (18432 * 4)   // 73728 bytes
__global__ __launch_bounds__(256, 2) void qkv_mma(const float* __restrict__ x)
{
    extern __shared__ uint32_t sm[];
    const int tid = threadIdx.x;
    const int w = tid >> 5, lane = tid & 31;
    const int g = lane >> 2, t = lane & 3;
    const int wm = w >> 2, wn = w & 3;
    const int m0 = blockIdx.x * 64;

    float4 acc[2][6];
    #pragma unroll
    for (int i = 0; i < 2; i++)
        #pragma unroll
        for (int j = 0; j < 6; j++) acc[i][j] = make_float4(0.f, 0.f, 0.f, 0.f);

    const int ar = tid >> 2, aq0 = tid & 3;
    const int asw = ar & 3;
    const bool bldr = (tid < 192);
    const uint32_t sbase = smem_u32(sm);
    const float* xsrc0 = x + (size_t)(m0 + ar) * Cc + aq0 * 4;
    const uint32_t* bsrc = g_Bpk + tid * 16;
    const uint32_t xdst0 = sbase + (2048u + (uint32_t)(ar * 16 + aq0 * 4)) * 4;
    const uint32_t bdst0 = sbase + (6144u + (uint32_t)tid * 16) * 4;

    // prologue: groups for chunks 0,1,2
    #pragma unroll
    for (int c = 0; c < 3; c++) {
        cpa16(xdst0 + (uint32_t)c * 4096u, xsrc0 + c * 16);
        if (bldr) {
            const uint32_t* src = bsrc + (size_t)c * 3072;
            const uint32_t dst = bdst0 + (uint32_t)c * 12288u;
            #pragma unroll
            for (int j = 0; j < 4; j++) cpa16(dst + j * 16, src + j * 4);
        }
        CP_COMMIT();
    }

    const int fsw = ((t ^ (g & 3)) << 2);
    const int raw_ = (wm * 32 + g) * 16;
    const int rbw  = (wn * 48 + g) * 16;
    const uint32_t* xrd = sm + 2048 + ar * 16 + aq0 * 4;

    #pragma unroll 1
    for (int ch = 0; ch < 64; ch++) {
        const int s2 = ch & 1, s4 = ch & 3;
        CP_WAIT2();   // group(ch) complete (incl. this thread's own x chunk)
        // cvt raw x -> swizzled A-frag (RNA points identical to before)
        const uint4 xv = *(const uint4*)(xrd + s4 * 1024);
        uint32_t* A = sm + s2 * 1024 + ar * 16 + aq0;
        A[((0 ^ asw) << 2)] = tf32r(__uint_as_float(xv.x));
        A[((1 ^ asw) << 2)] = tf32r(__uint_as_float(xv.y));
        A[((2 ^ asw) << 2)] = tf32r(__uint_as_float(xv.z));
        A[((3 ^ asw) << 2)] = tf32r(__uint_as_float(xv.w));
        __syncthreads();
        if (ch < 61) {
            const int cn = ch + 3, sn = cn & 3;
            cpa16(xdst0 + (uint32_t)sn * 4096u, xsrc0 + cn * 16);
            if (bldr) {
                const uint32_t* src = bsrc + (size_t)cn * 3072;
                const uint32_t dst = bdst0 + (uint32_t)sn * 12288u;
                #pragma unroll
                for (int j = 0; j < 4; j++) cpa16(dst + j * 16, src + j * 4);
            }
        }
        CP_COMMIT();   // empty groups in the tail keep wait_group counts uniform
        // fragments: uint4 = k in {t, t+4, t+8, t+12} (R11, conflict-free)
        const uint32_t* Ap = sm + s2 * 1024 + raw_ + fsw;
        const uint4 A0a = *(const uint4*)(Ap);
        const uint4 A8a = *(const uint4*)(Ap + 128);
        const uint4 A0b = *(const uint4*)(Ap + 256);
        const uint4 A8b = *(const uint4*)(Ap + 384);
        const uint32_t* Bp = sm + 6144 + s4 * 3072 + rbw + fsw;
        #pragma unroll
        for (int ns = 0; ns < 6; ns++) {
            const uint4 Bv = *(const uint4*)(Bp + ns * 128);
            mma8(acc[0][ns], A0a.x, A8a.x, A0a.y, A8a.y, Bv.x, Bv.y);   // kk=0
            mma8(acc[0][ns], A0a.z, A8a.z, A0a.w, A8a.w, Bv.z, Bv.w);   // kk=1
            mma8(acc[1][ns], A0b.x, A8b.x, A0b.y, A8b.y, Bv.x, Bv.y);
            mma8(acc[1][ns], A0b.z, A8b.z, A0b.w, A8b.w, Bv.z, Bv.w);
        }
    }
    // epilogue (R11): Q raw; K,V tf32-rounded plain layout
    #pragma unroll
    for (int sub = 0; sub < 2; sub++) {
        #pragma unroll
        for (int ns = 0; ns < 6; ns++) {
            const int cb = wn * 48 + ns * 8;
            float* base = (cb < 64) ? g_Q : (cb < 128) ? g_K : g_V;
            const bool rnd = (cb >= 64);
            const int c = (cb & 63) + 2 * t;
            const size_t r = (size_t)(m0 + wm * 32 + sub * 16 + g);
            float4 v = acc[sub][ns];
            if (rnd) {
                v.x = __uint_as_float(tf32r(v.x)); v.y = __uint_as_float(tf32r(v.y));
                v.z = __uint_as_float(tf32r(v.z)); v.w = __uint_as_float(tf32r(v.w));
            }
            *(float2*)(base + r * HS + c)       = make_float2(v.x, v.y);
            *(float2*)(base + (r + 8) * HS + c) = make_float2(v.z, v.w);
        }
    }
}

// ============================================================================
// Split-KV causal attention (exact R8 best): fused per-8-key S->softmax->PV,
// 2 CTAs/SM, K/V staged raw via cp.async, scalar fragment gathers.
// ============================================================================
#define KLDK 68
#define KLDV 72
#define SMEM_ATTN ((128 * KLDK + 128 * KLDV) * 4)

__global__ __launch_bounds__(256, 2) void attn_part(void)
{
    extern __shared__ uint32_t smv[];
    uint32_t* Ks = smv;
    uint32_t* Vs = smv + 128 * KLDK;
    const uint32_t ks_b = smem_u32(Ks), vs_b = smem_u32(Vs);

    const int item = (gridDim.x - 1) - blockIdx.x;
    const int b = item / WPB;
    int r = item % WPB, rb = 0;
    #pragma unroll 1
    while (true) { int n = (rb + CH) >> 2; if (r < n) break; r -= n; rb++; }
    const int chunk = r;
    const int t0 = chunk * CH;
    const int t1 = (t0 + CH < rb + 1) ? (t0 + CH) : (rb + 1);
    const int qbase = rb * 128;

    const int tid = threadIdx.x;
    const int w = tid >> 5, lane = tid & 31;
    const int g = lane >> 2, t = lane & 3;
    const int qrow_lo = qbase + w * 16 + g;
    const int qrow_hi = qrow_lo + 8;

    const float qscale = 1.4426950408889634f / 32.0f;
    uint32_t aq[8][4];
    {
        const float* r0 = g_Q + ((size_t)b * Tt + qrow_lo) * HS;
        const float* r1 = r0 + 8 * HS;
        #pragma unroll
        for (int kk = 0; kk < 8; kk++) {
            aq[kk][0] = tf32r(r0[kk * 8 + t] * qscale);
            aq[kk][1] = tf32r(r1[kk * 8 + t] * qscale);
            aq[kk][2] = tf32r(r0[kk * 8 + t + 4] * qscale);
            aq[kk][3] = tf32r(r1[kk * 8 + t + 4] * qscale);
        }
    }

    float4 acc_o[8];
    #pragma unroll
    for (int i = 0; i < 8; i++) acc_o[i] = make_float4(0.f, 0.f, 0.f, 0.f);
    float lsum_lo = 0.f, lsum_hi = 0.f;

    const float* Kg = g_K + (size_t)b * Tt * HS;
    const float* Vg = g_V + (size_t)b * Tt * HS;
    const int srcq0 = (lane & ~3) | (t >> 1);
    const int srcq1 = srcq0 | 2;
    const bool odd = (t & 1);

    #pragma unroll 1
    for (int tt = t0; tt < t1; tt++) {
        const int j0 = tt * 128;
        __syncthreads();
        #pragma unroll
        for (int i = 0; i < 8; i++) {
            int u = tid + i * 256;
            int rr = u >> 4, c = (u & 15) * 4;
            cpa16(ks_b + (uint32_t)(rr * KLDK + c) * 4, Kg + (size_t)(j0 + rr) * HS + c);
            cpa16(vs_b + (uint32_t)(rr * KLDV + c) * 4, Vg + (size_t)(j0 + rr) * HS + c);
        }
        CP_COMMIT();
        CP_WAIT0();
        __syncthreads();

        const bool last_tile = (tt == rb);
        #pragma unroll 1
        for (int ns = 0; ns < 16; ns++) {
            float4 cs = make_float4(0.f, 0.f, 0.f, 0.f);
            #pragma unroll
            for (int kk = 0; kk < 8; kk++) {
                uint32_t b0 = Ks[(ns * 8 + g) * KLDK + kk * 8 + t];
                uint32_t b1 = Ks[(ns * 8 + g) * KLDK + kk * 8 + t + 4];
                mma8(cs, aq[kk][0], aq[kk][1], aq[kk][2], aq[kk][3], b0, b1);
            }
            float px = ex2f(cs.x), py = ex2f(cs.y), pz = ex2f(cs.z), pw = ex2f(cs.w);
            if (last_tile) {
                const int cx = j0 + ns * 8 + 2 * t, cy = cx + 1;
                if (cx > qrow_lo) px = 0.f;
                if (cy > qrow_lo) py = 0.f;
                if (cx > qrow_hi) pz = 0.f;
                if (cy > qrow_hi) pw = 0.f;
            }
            uint32_t ux = tf32r(px), uy = tf32r(py), uz = tf32r(pz), uw = tf32r(pw);
            lsum_lo += __uint_as_float(ux) + __uint_as_float(uy);
            lsum_hi += __uint_as_float(uz) + __uint_as_float(uw);
            uint32_t xA = __shfl_sync(0xffffffffu, ux, srcq0);
            uint32_t yA = __shfl_sync(0xffffffffu, uy, srcq0);
            uint32_t zA = __shfl_sync(0xffffffffu, uz, srcq0);
            uint32_t wA = __shfl_sync(0xffffffffu, uw, srcq0);
            uint32_t xB = __shfl_sync(0xffffffffu, ux, srcq1);
            uint32_t yB = __shfl_sync(0xffffffffu, uy, srcq1);
            uint32_t zB = __shfl_sync(0xffffffffu, uz, srcq1);
            uint32_t wB = __shfl_sync(0xffffffffu, uw, srcq1);
            uint32_t a0 = odd ? yA : xA;
            uint32_t a1 = odd ? wA : zA;
            uint32_t a2 = odd ? yB : xB;
            uint32_t a3 = odd ? wB : zB;
            #pragma unroll
            for (int ns2 = 0; ns2 < 8; ns2++) {
                uint32_t b0 = Vs[(ns * 8 + t) * KLDV + ns2 * 8 + g];
                uint32_t b1 = Vs[(ns * 8 + t + 4) * KLDV + ns2 * 8 + g];
                mma8(acc_o[ns2], a0, a1, a2, a3, b0, b1);
            }
        }
    }

    float llo = lsum_lo;
    llo += __shfl_xor_sync(0xffffffffu, llo, 1);
    llo += __shfl_xor_sync(0xffffffffu, llo, 2);
    float lhi = lsum_hi;
    lhi += __shfl_xor_sync(0xffffffffu, lhi, 1);
    lhi += __shfl_xor_sync(0xffffffffu, lhi, 2);

    float* baseo = g_Op + (((size_t)chunk * Bb + b) * Tt + qrow_lo) * HS;
    #pragma unroll
    for (int ns2 = 0; ns2 < 8; ns2++) {
        *(float2*)(baseo + ns2 * 8 + 2 * t)          = make_float2(acc_o[ns2].x, acc_o[ns2].y);
        *(float2*)(baseo + 8 * HS + ns2 * 8 + 2 * t) = make_float2(acc_o[ns2].z, acc_o[ns2].w);
    }
    if (t == 0) {
        g_Lp[((size_t)chunk * Bb + b) * Tt + qrow_lo] = llo;
        g_Lp[((size_t)chunk * Bb + b) * Tt + qrow_hi] = lhi;
    }
}

// ============================================================================
// Combine (R8): float4/thread, <=4 slots.
// ============================================================================
__global__ __launch_bounds__(256) void attn_combine(float* __restrict__ out)
{
    const int idx4 = blockIdx.x * 256 + threadIdx.x;
    const int row  = idx4 >> 4;
    const int d4   = (idx4 & 15) * 4;
    const int trow = row & (Tt - 1);
    const int b    = row >> 11;
    const int rb   = trow >> 7;
    const int nch  = (rb + CH) >> 2;

    float4 o = make_float4(0.f, 0.f, 0.f, 0.f);
    float l = 0.f;
    #pragma unroll
    for (int s = 0; s < NSLOT; s++) {
        if (s < nch) {
            float4 v = *(const float4*)(g_Op + (((size_t)s * Bb + b) * Tt + trow) * HS + d4);
            o.x += v.x; o.y += v.y; o.z += v.z; o.w += v.w;
            l += g_Lp[((size_t)s * Bb + b) * Tt + trow];
        }
    }
    const float rl = 1.0f / l;
    *(float4*)(out + (size_t)row * HS + d4) =
        make_float4(o.x * rl, o.y * rl, o.z * rl, o.w * rl);
}

// ============================================================================
extern "C" void kernel_launch(void* const* d_in, const int* in_sizes, int n_in,
                              void* d_out, int out_size)
{
    const float* x  = (const float*)d_in[0];
    const float* Wq = (const float*)d_in[1];
    const float* Wk = (const float*)d_in[2];
    const float* Wv = (const float*)d_in[3];
    float* out = (float*)d_out;

    prep_b<<<64, 256>>>(Wq, Wk, Wv);

    cudaFuncSetAttribute(qkv_mma, cudaFuncAttributeMaxDynamicSharedMemorySize, QKV_SMEM);
    qkv_mma<<<(Bb * Tt) / 64, 256, QKV_SMEM>>>(x);

    cudaFuncSetAttribute(attn_part, cudaFuncAttributeMaxDynamicSharedMemorySize, SMEM_ATTN);
    attn_part<<<Bb * WPB, 256, SMEM_ATTN>>>();

    attn_combine<<<(Bb * Tt * (HS / 4)) / 256, 256>>>(out);
}

// round 17
// speedup vs baseline: 1.4333x; 1.0974x over previous
#include <cuda_runtime.h>
#include <cuda_fp16.h>
#include <cstdint>

#define Bb 8
#define Tt 2048
#define Cc 1024
#define HS 64
#define CH 4              // key-tiles (128 keys) per split-KV chunk
#define NSLOT 4
#define WPB 40            // sum_{rb=0}^{15} ceil((rb+1)/4)

__device__ __align__(16) float g_Q[Bb*Tt*HS];
__device__ __align__(16) float g_K[Bb*Tt*HS];        // tf32-rounded
__device__ __align__(16) __half g_Vt[Bb*HS*Tt];      // fp16, transposed [b][dim][key]
__device__ __align__(16) float g_Op[NSLOT*Bb*Tt*HS];
__device__ __align__(16) float g_Lp[NSLOT*Bb*Tt];
__device__ __align__(16) uint32_t g_Bpk[64 * 3072];  // 64 k-chunks x 192 n-rows x 16 words

__device__ __forceinline__ uint32_t tf32r(float f) {
    uint32_t r; asm("cvt.rna.tf32.f32 %0, %1;" : "=r"(r) : "f"(f)); return r;
}
__device__ __forceinline__ float ex2f(float x) {
    float r; asm("ex2.approx.f32 %0, %1;" : "=f"(r) : "f"(x)); return r;
}
__device__ __forceinline__ uint32_t packh(float lo, float hi) {
    uint32_t r; asm("cvt.rn.f16x2.f32 %0, %2, %1;" : "=r"(r) : "f"(lo), "f"(hi)); return r;
}
__device__ __forceinline__ void mma8(float4& d, uint32_t a0, uint32_t a1, uint32_t a2, uint32_t a3,
                                     uint32_t b0, uint32_t b1) {
    asm("mma.sync.aligned.m16n8k8.row.col.f32.tf32.tf32.f32 "
        "{%0,%1,%2,%3}, {%4,%5,%6,%7}, {%8,%9}, {%0,%1,%2,%3};"
        : "+f"(d.x), "+f"(d.y), "+f"(d.z), "+f"(d.w)
        : "r"(a0), "r"(a1), "r"(a2), "r"(a3), "r"(b0), "r"(b1));
}
__device__ __forceinline__ void mma16h(float4& d, uint32_t a0, uint32_t a1, uint32_t a2, uint32_t a3,
                                       uint32_t b0, uint32_t b1) {
    asm("mma.sync.aligned.m16n8k16.row.col.f32.f16.f16.f32 "
        "{%0,%1,%2,%3}, {%4,%5,%6,%7}, {%8,%9}, {%0,%1,%2,%3};"
        : "+f"(d.x), "+f"(d.y), "+f"(d.z), "+f"(d.w)
        : "r"(a0), "r"(a1), "r"(a2), "r"(a3), "r"(b0), "r"(b1));
}
__device__ __forceinline__ uint32_t smem_u32(const void* p) {
    uint32_t a;
    asm("{ .reg .u64 t; cvta.to.shared.u64 t, %1; cvt.u32.u64 %0, t; }" : "=r"(a) : "l"(p));
    return a;
}
__device__ __forceinline__ void cpa16(uint32_t dst, const void* src) {
    asm volatile("cp.async.cg.shared.global [%0], [%1], 16;" :: "r"(dst), "l"(src));
}
#define CP_COMMIT() asm volatile("cp.async.commit_group;" ::: "memory")
#define CP_WAIT0()  asm volatile("cp.async.wait_group 0;" ::: "memory")
#define CP_WAIT2()  asm volatile("cp.async.wait_group 2;" ::: "memory")

// ============================================================================
// Prep (unchanged): weights -> permuted + XOR-swizzled tf32 image.
// ============================================================================
__global__ __launch_bounds__(256) void prep_b(
    const float* __restrict__ Wq, const float* __restrict__ Wk, const float* __restrict__ Wv)
{
    const int ch = blockIdx.x;
    #pragma unroll
    for (int i = 0; i < 12; i++) {
        const int idx = threadIdx.x + i * 256;    // 0..3071
        const int n = idx >> 4, wd = idx & 15;
        const int k = ((wd & 3) << 2) | ((wd >> 2) ^ (n & 3));
        const float* W = (n < 64) ? Wq : (n < 128) ? Wk : Wv;
        g_Bpk[ch * 3072 + idx] = tf32r(W[(size_t)(ch * 16 + k) * HS + (n & 63)]);
    }
}

// ============================================================================
// Fused QKV (R16 body): CTA 64x192, all global traffic via 4-stage cp.async
// rings (wait_group 2). Epilogue: Q raw; K tf32-rounded; V fp16 transposed.
// ============================================================================
#define QKV_SMEM (18432 * 4)   // 73728 bytes
__global__ __launch_bounds__(256, 2) void qkv_mma(const float* __restrict__ x)
{
    extern __shared__ uint32_t sm[];
    const int tid = threadIdx.x;
    const int w = tid >> 5, lane = tid & 31;
    const int g = lane >> 2, t = lane & 3;
    const int wm = w >> 2, wn = w & 3;
    const int m0 = blockIdx.x * 64;

    float4 acc[2][6];
    #pragma unroll
    for (int i = 0; i < 2; i++)
        #pragma unroll
        for (int j = 0; j < 6; j++) acc[i][j] = make_float4(0.f, 0.f, 0.f, 0.f);

    const int ar = tid >> 2, aq0 = tid & 3;
    const int asw = ar & 3;
    const bool bldr = (tid < 192);
    const uint32_t sbase = smem_u32(sm);
    const float* xsrc0 = x + (size_t)(m0 + ar) * Cc + aq0 * 4;
    const uint32_t* bsrc = g_Bpk + tid * 16;
    const uint32_t xdst0 = sbase + (2048u + (uint32_t)(ar * 16 + aq0 * 4)) * 4;
    const uint32_t bdst0 = sbase + (6144u + (uint32_t)tid * 16) * 4;

    #pragma unroll
    for (int c = 0; c < 3; c++) {
        cpa16(xdst0 + (uint32_t)c * 4096u, xsrc0 + c * 16);
        if (bldr) {
            const uint32_t* src = bsrc + (size_t)c * 3072;
            const uint32_t dst = bdst0 + (uint32_t)c * 12288u;
            #pragma unroll
            for (int j = 0; j < 4; j++) cpa16(dst + j * 16, src + j * 4);
        }
        CP_COMMIT();
    }

    const int fsw = ((t ^ (g & 3)) << 2);
    const int raw_ = (wm * 32 + g) * 16;
    const int rbw  = (wn * 48 + g) * 16;
    const uint32_t* xrd = sm + 2048 + ar * 16 + aq0 * 4;

    #pragma unroll 1
    for (int ch = 0; ch < 64; ch++) {
        const int s2 = ch & 1, s4 = ch & 3;
        CP_WAIT2();
        const uint4 xv = *(const uint4*)(xrd + s4 * 1024);
        uint32_t* A = sm + s2 * 1024 + ar * 16 + aq0;
        A[((0 ^ asw) << 2)] = tf32r(__uint_as_float(xv.x));
        A[((1 ^ asw) << 2)] = tf32r(__uint_as_float(xv.y));
        A[((2 ^ asw) << 2)] = tf32r(__uint_as_float(xv.z));
        A[((3 ^ asw) << 2)] = tf32r(__uint_as_float(xv.w));
        __syncthreads();
        if (ch < 61) {
            const int cn = ch + 3, sn = cn & 3;
            cpa16(xdst0 + (uint32_t)sn * 4096u, xsrc0 + cn * 16);
            if (bldr) {
                const uint32_t* src = bsrc + (size_t)cn * 3072;
                const uint32_t dst = bdst0 + (uint32_t)sn * 12288u;
                #pragma unroll
                for (int j = 0; j < 4; j++) cpa16(dst + j * 16, src + j * 4);
            }
        }
        CP_COMMIT();
        const uint32_t* Ap = sm + s2 * 1024 + raw_ + fsw;
        const uint4 A0a = *(const uint4*)(Ap);
        const uint4 A8a = *(const uint4*)(Ap + 128);
        const uint4 A0b = *(const uint4*)(Ap + 256);
        const uint4 A8b = *(const uint4*)(Ap + 384);
        const uint32_t* Bp = sm + 6144 + s4 * 3072 + rbw + fsw;
        #pragma unroll
        for (int ns = 0; ns < 6; ns++) {
            const uint4 Bv = *(const uint4*)(Bp + ns * 128);
            mma8(acc[0][ns], A0a.x, A8a.x, A0a.y, A8a.y, Bv.x, Bv.y);
            mma8(acc[0][ns], A0a.z, A8a.z, A0a.w, A8a.w, Bv.z, Bv.w);
            mma8(acc[1][ns], A0b.x, A8b.x, A0b.y, A8b.y, Bv.x, Bv.y);
            mma8(acc[1][ns], A0b.z, A8b.z, A0b.w, A8b.w, Bv.z, Bv.w);
        }
    }
    // epilogue: Q raw; K tf32-rounded; V fp16 transposed [b][dim][key]
    #pragma unroll
    for (int sub = 0; sub < 2; sub++) {
        #pragma unroll
        for (int ns = 0; ns < 6; ns++) {
            const int cb = wn * 48 + ns * 8;
            const int c = (cb & 63) + 2 * t;
            const size_t r = (size_t)(m0 + wm * 32 + sub * 16 + g);
            float4 v = acc[sub][ns];
            if (cb < 64) {
                *(float2*)(g_Q + r * HS + c)       = make_float2(v.x, v.y);
                *(float2*)(g_Q + (r + 8) * HS + c) = make_float2(v.z, v.w);
            } else if (cb < 128) {
                v.x = __uint_as_float(tf32r(v.x)); v.y = __uint_as_float(tf32r(v.y));
                v.z = __uint_as_float(tf32r(v.z)); v.w = __uint_as_float(tf32r(v.w));
                *(float2*)(g_K + r * HS + c)       = make_float2(v.x, v.y);
                *(float2*)(g_K + (r + 8) * HS + c) = make_float2(v.z, v.w);
            } else {
                const size_t b = r >> 11, trow = r & (Tt - 1);
                __half* vb = g_Vt + b * HS * Tt;
                vb[(size_t)c * Tt + trow]           = __float2half_rn(v.x);
                vb[(size_t)(c + 1) * Tt + trow]     = __float2half_rn(v.y);
                vb[(size_t)c * Tt + trow + 8]       = __float2half_rn(v.z);
                vb[(size_t)(c + 1) * Tt + trow + 8] = __float2half_rn(v.w);
            }
        }
    }
}

// ============================================================================
// Split-KV causal attention: S via tf32 (identical to R16); P packed fp16x2
// directly from the C-fragment (NO shuffles); PV via m16n8k16.f16 on fp16 V
// (transposed layout, key-pairs lo/hi in one word). 2 CTAs/SM.
// ============================================================================
#define KLDK 68
#define LDV  68
#define SMEM_ATTN ((128 * KLDK + 64 * LDV) * 4)

__global__ __launch_bounds__(256, 2) void attn_part(void)
{
    extern __shared__ uint32_t smv[];
    uint32_t* Ks = smv;
    uint32_t* Vs = smv + 128 * KLDK;
    const uint32_t ks_b = smem_u32(Ks), vs_b = smem_u32(Vs);

    const int item = (gridDim.x - 1) - blockIdx.x;
    const int b = item / WPB;
    int r = item % WPB, rb = 0;
    #pragma unroll 1
    while (true) { int n = (rb + CH) >> 2; if (r < n) break; r -= n; rb++; }
    const int chunk = r;
    const int t0 = chunk * CH;
    const int t1 = (t0 + CH < rb + 1) ? (t0 + CH) : (rb + 1);
    const int qbase = rb * 128;

    const int tid = threadIdx.x;
    const int w = tid >> 5, lane = tid & 31;
    const int g = lane >> 2, t = lane & 3;
    const int qrow_lo = qbase + w * 16 + g;
    const int qrow_hi = qrow_lo + 8;

    const float qscale = 1.4426950408889634f / 32.0f;
    uint32_t aq[8][4];
    {
        const float* r0 = g_Q + ((size_t)b * Tt + qrow_lo) * HS;
        const float* r1 = r0 + 8 * HS;
        #pragma unroll
        for (int kk = 0; kk < 8; kk++) {
            aq[kk][0] = tf32r(r0[kk * 8 + t] * qscale);
            aq[kk][1] = tf32r(r1[kk * 8 + t] * qscale);
            aq[kk][2] = tf32r(r0[kk * 8 + t + 4] * qscale);
            aq[kk][3] = tf32r(r1[kk * 8 + t + 4] * qscale);
        }
    }

    float4 acc_o[8];
    #pragma unroll
    for (int i = 0; i < 8; i++) acc_o[i] = make_float4(0.f, 0.f, 0.f, 0.f);
    float lsum_lo = 0.f, lsum_hi = 0.f;

    const float* Kg = g_K + (size_t)b * Tt * HS;
    const __half* Vtb = g_Vt + (size_t)b * HS * Tt;

    #pragma unroll 1
    for (int tt = t0; tt < t1; tt++) {
        const int j0 = tt * 128;
        __syncthreads();
        // K: 128 rows x 64 words (tf32)
        #pragma unroll
        for (int i = 0; i < 8; i++) {
            int u = tid + i * 256;
            int rr = u >> 4, c = (u & 15) * 4;
            cpa16(ks_b + (uint32_t)(rr * KLDK + c) * 4, Kg + (size_t)(j0 + rr) * HS + c);
        }
        // V: 64 dim-rows x 64 words (fp16 key pairs); 16B = 8 keys
        #pragma unroll
        for (int i = 0; i < 4; i++) {
            int u = tid + i * 256;
            int dim = u >> 4, c4 = u & 15;
            cpa16(vs_b + (uint32_t)(dim * LDV + c4 * 4) * 4,
                  Vtb + (size_t)dim * Tt + j0 + c4 * 8);
        }
        CP_COMMIT();
        CP_WAIT0();
        __syncthreads();

        const bool last_tile = (tt == rb);
        #pragma unroll 1
        for (int np = 0; np < 8; np++) {          // 16-key groups
            uint32_t pa[4];
            #pragma unroll
            for (int hf = 0; hf < 2; hf++) {      // two 8-key S subtiles
                const int ns = 2 * np + hf;
                float4 cs = make_float4(0.f, 0.f, 0.f, 0.f);
                #pragma unroll
                for (int kk = 0; kk < 8; kk++) {
                    uint32_t b0 = Ks[(ns * 8 + g) * KLDK + kk * 8 + t];
                    uint32_t b1 = Ks[(ns * 8 + g) * KLDK + kk * 8 + t + 4];
                    mma8(cs, aq[kk][0], aq[kk][1], aq[kk][2], aq[kk][3], b0, b1);
                }
                float px = ex2f(cs.x), py = ex2f(cs.y), pz = ex2f(cs.z), pw = ex2f(cs.w);
                if (last_tile) {
                    const int cx = j0 + ns * 8 + 2 * t, cy = cx + 1;
                    if (cx > qrow_lo) px = 0.f;
                    if (cy > qrow_lo) py = 0.f;
                    if (cx > qrow_hi) pz = 0.f;
                    if (cy > qrow_hi) pw = 0.f;
                }
                lsum_lo += px + py;
                lsum_hi += pz + pw;
                pa[2 * hf]     = packh(px, py);   // row g,   keys (2t,2t+1) of this k8
                pa[2 * hf + 1] = packh(pz, pw);   // row g+8
            }
            // PV: m16n8k16.f16, A = {pa[0],pa[2] -> k-groups 0,1 rows g; pa[1],pa[3] rows g+8}
            #pragma unroll
            for (int ns2 = 0; ns2 < 8; ns2++) {
                uint32_t b0 = Vs[(ns2 * 8 + g) * LDV + np * 8 + t];
                uint32_t b1 = Vs[(ns2 * 8 + g) * LDV + np * 8 + t + 4];
                mma16h(acc_o[ns2], pa[0], pa[1], pa[2], pa[3], b0, b1);
            }
        }
    }

    float llo = lsum_lo;
    llo += __shfl_xor_sync(0xffffffffu, llo, 1);
    llo += __shfl_xor_sync(0xffffffffu, llo, 2);
    float lhi = lsum_hi;
    lhi += __shfl_xor_sync(0xffffffffu, lhi, 1);
    lhi += __shfl_xor_sync(0xffffffffu, lhi, 2);

    float* baseo = g_Op + (((size_t)chunk * Bb + b) * Tt + qrow_lo) * HS;
    #pragma unroll
    for (int ns2 = 0; ns2 < 8; ns2++) {
        *(float2*)(baseo + ns2 * 8 + 2 * t)          = make_float2(acc_o[ns2].x, acc_o[ns2].y);
        *(float2*)(baseo + 8 * HS + ns2 * 8 + 2 * t) = make_float2(acc_o[ns2].z, acc_o[ns2].w);
    }
    if (t == 0) {
        g_Lp[((size_t)chunk * Bb + b) * Tt + qrow_lo] = llo;
        g_Lp[((size_t)chunk * Bb + b) * Tt + qrow_hi] = lhi;
    }
}

// ============================================================================
// Combine (unchanged): float4/thread, <=4 slots.
// ============================================================================
__global__ __launch_bounds__(256) void attn_combine(float* __restrict__ out)
{
    const int idx4 = blockIdx.x * 256 + threadIdx.x;
    const int row  = idx4 >> 4;
    const int d4   = (idx4 & 15) * 4;
    const int trow = row & (Tt - 1);
    const int b    = row >> 11;
    const int rb   = trow >> 7;
    const int nch  = (rb + CH) >> 2;

    float4 o = make_float4(0.f, 0.f, 0.f, 0.f);
    float l = 0.f;
    #pragma unroll
    for (int s = 0; s < NSLOT; s++) {
        if (s < nch) {
            float4 v = *(const float4*)(g_Op + (((size_t)s * Bb + b) * Tt + trow) * HS + d4);
            o.x += v.x; o.y += v.y; o.z += v.z; o.w += v.w;
            l += g_Lp[((size_t)s * Bb + b) * Tt + trow];
        }
    }
    const float rl = 1.0f / l;
    *(float4*)(out + (size_t)row * HS + d4) =
        make_float4(o.x * rl, o.y * rl, o.z * rl, o.w * rl);
}

// ============================================================================
extern "C" void kernel_launch(void* const* d_in, const int* in_sizes, int n_in,
                              void* d_out, int out_size)
{
    const float* x  = (const float*)d_in[0];
    const float* Wq = (const float*)d_in[1];
    const float* Wk = (const float*)d_in[2];
    const float* Wv = (const float*)d_in[3];
    float* out = (float*)d_out;

    prep_b<<<64, 256>>>(Wq, Wk, Wv);

    cudaFuncSetAttribute(qkv_mma, cudaFuncAttributeMaxDynamicSharedMemorySize, QKV_SMEM);
    qkv_mma<<<(Bb * Tt) / 64, 256, QKV_SMEM>>>(x);

    cudaFuncSetAttribute(attn_part, cudaFuncAttributeMaxDynamicSharedMemorySize, SMEM_ATTN);
    attn_part<<<Bb * WPB, 256, SMEM_ATTN>>>();

    attn_combine<<<(Bb * Tt * (HS / 4)) / 256, 256>>>(out);
}